// round 1
// baseline (speedup 1.0000x reference)
#include <cuda_runtime.h>

// Problem constants (fixed by the reference)
#define SLEN 4096
#define NSTR 4
#define DIMV 1024
#define D4   256          // DIMV / 4 (float4)
#define NCH  32           // s-chunks for pass-1 reduction
#define SPC  128          // SLEN / NCH
#define EPSV 1e-6f

// Deterministic scratch (no cudaMalloc allowed)
__device__ float g_partials[NCH * NSTR * NSTR * DIMV]; // [chunk][b][n][d]  (2 MB)
__device__ float g_x[NSTR * NSTR * DIMV];              // mean: [b][n*1024+d]
__device__ float g_coefs[NSTR * 24];                   // per-b: pre[4], post[4], res[16]

// ---------------------------------------------------------------------------
// Kernel 1: partial sums of H over s within a chunk.
// grid = (NCH, NSTR, NSTR), block = 256 (one thread per float4 of d)
// ---------------------------------------------------------------------------
__global__ __launch_bounds__(256) void k_reduce1(const float4* __restrict__ H4) {
    const int t = threadIdx.x;          // d4 index
    const int c = blockIdx.x;           // s-chunk
    const int n = blockIdx.y;
    const int b = blockIdx.z;
    const float4* p = H4 + ((size_t)(b * SLEN + c * SPC) * NSTR + n) * D4 + t;
    const size_t stride = (size_t)NSTR * D4;   // one s step

    float4 a0 = make_float4(0.f,0.f,0.f,0.f), a1 = a0, a2 = a0, a3 = a0;
    for (int i = 0; i < SPC; i += 4) {
        float4 v0 = p[(size_t)(i+0) * stride];
        float4 v1 = p[(size_t)(i+1) * stride];
        float4 v2 = p[(size_t)(i+2) * stride];
        float4 v3 = p[(size_t)(i+3) * stride];
        a0.x += v0.x; a0.y += v0.y; a0.z += v0.z; a0.w += v0.w;
        a1.x += v1.x; a1.y += v1.y; a1.z += v1.z; a1.w += v1.w;
        a2.x += v2.x; a2.y += v2.y; a2.z += v2.z; a2.w += v2.w;
        a3.x += v3.x; a3.y += v3.y; a3.z += v3.z; a3.w += v3.w;
    }
    float4 r;
    r.x = (a0.x + a1.x) + (a2.x + a3.x);
    r.y = (a0.y + a1.y) + (a2.y + a3.y);
    r.z = (a0.z + a1.z) + (a2.z + a3.z);
    r.w = (a0.w + a1.w) + (a2.w + a3.w);
    float4* out = reinterpret_cast<float4*>(g_partials);
    out[((c * NSTR + b) * NSTR + n) * D4 + t] = r;
}

// ---------------------------------------------------------------------------
// Kernel 2: fold chunk partials -> mean x[b][n*1024+d]
// grid = 64, block = 256 (one thread per output element)
// ---------------------------------------------------------------------------
__global__ __launch_bounds__(256) void k_reduce2() {
    const int k = blockIdx.x * 256 + threadIdx.x;   // 0..16383
    float s0 = 0.f, s1 = 0.f, s2 = 0.f, s3 = 0.f;
    #pragma unroll
    for (int c = 0; c < NCH; c += 4) {
        s0 += g_partials[(c+0) * 16384 + k];
        s1 += g_partials[(c+1) * 16384 + k];
        s2 += g_partials[(c+2) * 16384 + k];
        s3 += g_partials[(c+3) * 16384 + k];
    }
    g_x[k] = ((s0 + s1) + (s2 + s3)) * (1.0f / (float)SLEN);
}

// ---------------------------------------------------------------------------
// Kernel 3: tiny fused head: RMS, x@phi (phi tiled via smem), sigmoid,
// normalization, 20-iter sinkhorn on 4x4. Single block, 512 threads.
// Thread layout: group b = t>>7 (4 groups of 128 threads), warp w = t>>5.
// ---------------------------------------------------------------------------
__global__ __launch_bounds__(512) void k_small(
    const float* __restrict__ phi,
    const float* __restrict__ pre_base,
    const float* __restrict__ post_base,
    const float* __restrict__ res_base,
    const float* __restrict__ a_pre,
    const float* __restrict__ a_post,
    const float* __restrict__ a_res)
{
    __shared__ float phiS[256 * 25];   // tile of phi, padded stride 25 (bank-conflict free)
    __shared__ float wred[16 * 24];    // per-warp partial raw
    __shared__ float rawS[96];         // raw[b][j]
    __shared__ float warpred[16];
    __shared__ float ssqS[4];

    const int t    = threadIdx.x;
    const int b    = t >> 7;       // 0..3
    const int l    = t & 127;
    const int w    = t >> 5;       // 0..15
    const int lane = t & 31;

    // --- sum of squares per batch (for RMS) ---
    float s = 0.f;
    for (int k = l; k < 4096; k += 128) {
        float v = g_x[b * 4096 + k];
        s = fmaf(v, v, s);
    }
    #pragma unroll
    for (int off = 16; off > 0; off >>= 1)
        s += __shfl_down_sync(0xffffffffu, s, off);
    if (lane == 0) warpred[w] = s;
    __syncthreads();
    if (t < 4)
        ssqS[t] = warpred[t*4] + warpred[t*4+1] + warpred[t*4+2] + warpred[t*4+3];

    // --- raw[b][j] = sum_k x[b,k] * phi[k,j], 16 tiles of 256 k values ---
    float acc[24];
    #pragma unroll
    for (int j = 0; j < 24; j++) acc[j] = 0.f;

    for (int tile = 0; tile < 16; tile++) {
        __syncthreads();
        for (int i = t; i < 6144; i += 512) {
            int kk = i / 24;
            int j  = i - kk * 24;
            phiS[kk * 25 + j] = phi[tile * 6144 + i];
        }
        __syncthreads();
        for (int kk = l; kk < 256; kk += 128) {
            float xv = g_x[b * 4096 + tile * 256 + kk];
            int base = kk * 25;
            #pragma unroll
            for (int j = 0; j < 24; j++)
                acc[j] = fmaf(xv, phiS[base + j], acc[j]);
        }
    }
    #pragma unroll
    for (int j = 0; j < 24; j++) {
        float v = acc[j];
        #pragma unroll
        for (int off = 16; off > 0; off >>= 1)
            v += __shfl_down_sync(0xffffffffu, v, off);
        if (lane == 0) wred[w * 24 + j] = v;
    }
    __syncthreads();
    if (t < 96) {
        int bb = t / 24, j = t - bb * 24;
        rawS[t] = (wred[(bb*4+0)*24 + j] + wred[(bb*4+1)*24 + j])
                + (wred[(bb*4+2)*24 + j] + wred[(bb*4+3)*24 + j]);
    }
    __syncthreads();

    // --- per-batch finalize (threads 0..3, pure scalar) ---
    if (t < 4) {
        const int bb = t;
        float inv_rms = rsqrtf(ssqS[bb] * (1.0f / 4096.0f) + EPSV);
        float ap  = a_pre[0]  * inv_rms;
        float apo = a_post[0] * inv_rms;
        float ar  = a_res[0]  * inv_rms;
        const float* raw = &rawS[bb * 24];

        float pre[4], sum = 0.f;
        #pragma unroll
        for (int j = 0; j < 4; j++) {
            float v = fmaf(ap, raw[j], pre_base[j]);
            v = 1.0f / (1.0f + expf(-v));
            pre[j] = v; sum += v;
        }
        float inv = 1.0f / (sum + EPSV);

        float post[4];
        #pragma unroll
        for (int j = 0; j < 4; j++) {
            float v = fmaf(apo, raw[4 + j], post_base[j]);
            post[j] = 2.0f / (1.0f + expf(-v));
        }

        float P[16];
        #pragma unroll
        for (int j = 0; j < 16; j++)
            P[j] = fabsf(fmaf(ar, raw[8 + j], res_base[j])) + EPSV;
        for (int it = 0; it < 20; it++) {
            #pragma unroll
            for (int r = 0; r < 4; r++) {
                float rs = (P[4*r] + P[4*r+1]) + (P[4*r+2] + P[4*r+3]) + EPSV;
                float ir = 1.0f / rs;
                P[4*r] *= ir; P[4*r+1] *= ir; P[4*r+2] *= ir; P[4*r+3] *= ir;
            }
            #pragma unroll
            for (int cI = 0; cI < 4; cI++) {
                float cs = (P[cI] + P[4+cI]) + (P[8+cI] + P[12+cI]) + EPSV;
                float ic = 1.0f / cs;
                P[cI] *= ic; P[4+cI] *= ic; P[8+cI] *= ic; P[12+cI] *= ic;
            }
        }

        float* o = &g_coefs[bb * 24];
        #pragma unroll
        for (int j = 0; j < 4; j++)  o[j]     = pre[j] * inv;
        #pragma unroll
        for (int j = 0; j < 4; j++)  o[4 + j] = post[j];
        #pragma unroll
        for (int j = 0; j < 16; j++) o[8 + j] = P[j];
    }
}

// ---------------------------------------------------------------------------
// Kernel 4: stream mixing + residual + pack.
// grid = 16384 (b*s), block = 256 (one float4 of d per thread)
// out[b,s,0,d] = sum_n pre[n]*H[n];  out[b,s,1+n,d] = sum_m res[n][m]*H[m] + post[n]*bo
// ---------------------------------------------------------------------------
__global__ __launch_bounds__(256) void k_mix(const float4* __restrict__ H4,
                                             const float4* __restrict__ BO4,
                                             float4* __restrict__ out4) {
    __shared__ float c[24];
    const int bs = blockIdx.x;          // b*4096 + s
    const int b  = bs >> 12;
    const int t  = threadIdx.x;
    if (t < 24) c[t] = g_coefs[b * 24 + t];
    __syncthreads();

    const size_t hb = (size_t)bs * (NSTR * D4) + t;
    float4 h0 = H4[hb];
    float4 h1 = H4[hb + D4];
    float4 h2 = H4[hb + 2 * D4];
    float4 h3 = H4[hb + 3 * D4];
    float4 bo = BO4[(size_t)bs * D4 + t];

    const size_t ob = (size_t)bs * (5 * D4) + t;

    float4 r;
    r.x = fmaf(c[0], h0.x, fmaf(c[1], h1.x, fmaf(c[2], h2.x, c[3] * h3.x)));
    r.y = fmaf(c[0], h0.y, fmaf(c[1], h1.y, fmaf(c[2], h2.y, c[3] * h3.y)));
    r.z = fmaf(c[0], h0.z, fmaf(c[1], h1.z, fmaf(c[2], h2.z, c[3] * h3.z)));
    r.w = fmaf(c[0], h0.w, fmaf(c[1], h1.w, fmaf(c[2], h2.w, c[3] * h3.w)));
    out4[ob] = r;

    #pragma unroll
    for (int n = 0; n < 4; n++) {
        float r0 = c[8 + 4*n], r1 = c[9 + 4*n], r2 = c[10 + 4*n], r3 = c[11 + 4*n];
        float pp = c[4 + n];
        float4 o;
        o.x = fmaf(r0, h0.x, fmaf(r1, h1.x, fmaf(r2, h2.x, fmaf(r3, h3.x, pp * bo.x))));
        o.y = fmaf(r0, h0.y, fmaf(r1, h1.y, fmaf(r2, h2.y, fmaf(r3, h3.y, pp * bo.y))));
        o.z = fmaf(r0, h0.z, fmaf(r1, h1.z, fmaf(r2, h2.z, fmaf(r3, h3.z, pp * bo.z))));
        o.w = fmaf(r0, h0.w, fmaf(r1, h1.w, fmaf(r2, h2.w, fmaf(r3, h3.w, pp * bo.w))));
        out4[ob + (size_t)(1 + n) * D4] = o;
    }
}

// ---------------------------------------------------------------------------
// Inputs (metadata order): H, branch_output, phi, H_pre_base, H_post_base,
//                          H_res_base, alpha_pre, alpha_post, alpha_res
// ---------------------------------------------------------------------------
extern "C" void kernel_launch(void* const* d_in, const int* in_sizes, int n_in,
                              void* d_out, int out_size) {
    (void)in_sizes; (void)n_in; (void)out_size;
    const float4* H4  = (const float4*)d_in[0];
    const float4* BO4 = (const float4*)d_in[1];
    const float* phi  = (const float*)d_in[2];
    const float* preb = (const float*)d_in[3];
    const float* postb= (const float*)d_in[4];
    const float* resb = (const float*)d_in[5];
    const float* apre = (const float*)d_in[6];
    const float* apost= (const float*)d_in[7];
    const float* ares = (const float*)d_in[8];

    dim3 g1(NCH, NSTR, NSTR);
    k_reduce1<<<g1, 256>>>(H4);
    k_reduce2<<<64, 256>>>();
    k_small<<<1, 512>>>(phi, preb, postb, resb, apre, apost, ares);
    k_mix<<<16384, 256>>>(H4, BO4, (float4*)d_out);
}

// round 2
// speedup vs baseline: 1.2513x; 1.2513x over previous
#include <cuda_runtime.h>

// Problem constants (fixed by the reference)
#define SLEN 4096
#define NSTR 4
#define DIMV 1024
#define D4   256          // DIMV / 4 (float4)
#define NCH  32           // s-chunks for pass-1 reduction
#define SPC  128          // SLEN / NCH
#define EPSV 1e-6f

// Deterministic scratch (no cudaMalloc allowed)
__device__ float g_partials[NCH * NSTR * NSTR * DIMV]; // [chunk][b][n][d]  (2 MB)
__device__ float g_rawp[64 * 24];                      // per-block partial raw[b][j]
__device__ float g_ssqp[64];                           // per-block partial sum-of-squares
__device__ float g_coefs[NSTR * 24];                   // per-b: pre[4], post[4], res[16]

// ---------------------------------------------------------------------------
// Kernel 1: partial sums of H over s within a chunk.
// grid = (NCH, NSTR, NSTR), block = 256 (one thread per float4 of d)
// ---------------------------------------------------------------------------
__global__ __launch_bounds__(256) void k_reduce1(const float4* __restrict__ H4) {
    const int t = threadIdx.x;          // d4 index
    const int c = blockIdx.x;           // s-chunk
    const int n = blockIdx.y;
    const int b = blockIdx.z;
    const float4* p = H4 + ((size_t)(b * SLEN + c * SPC) * NSTR + n) * D4 + t;
    const size_t stride = (size_t)NSTR * D4;   // one s step

    float4 a0 = make_float4(0.f,0.f,0.f,0.f), a1 = a0, a2 = a0, a3 = a0;
    for (int i = 0; i < SPC; i += 4) {
        float4 v0 = p[(size_t)(i+0) * stride];
        float4 v1 = p[(size_t)(i+1) * stride];
        float4 v2 = p[(size_t)(i+2) * stride];
        float4 v3 = p[(size_t)(i+3) * stride];
        a0.x += v0.x; a0.y += v0.y; a0.z += v0.z; a0.w += v0.w;
        a1.x += v1.x; a1.y += v1.y; a1.z += v1.z; a1.w += v1.w;
        a2.x += v2.x; a2.y += v2.y; a2.z += v2.z; a2.w += v2.w;
        a3.x += v3.x; a3.y += v3.y; a3.z += v3.z; a3.w += v3.w;
    }
    float4 r;
    r.x = (a0.x + a1.x) + (a2.x + a3.x);
    r.y = (a0.y + a1.y) + (a2.y + a3.y);
    r.z = (a0.z + a1.z) + (a2.z + a3.z);
    r.w = (a0.w + a1.w) + (a2.w + a3.w);
    float4* out = reinterpret_cast<float4*>(g_partials);
    out[((c * NSTR + b) * NSTR + n) * D4 + t] = r;
}

// ---------------------------------------------------------------------------
// Kernel 2: fold chunk partials -> x (mean), AND compute per-block partial
// GEMV raw[b][j] = sum_m x[b,m]*phi[m,j] plus partial sum-of-squares.
// grid = 64 blocks, block = 256. Each block owns a contiguous 256-range of
// m within ONE batch b (4096 m per batch = 16 blocks per batch).
// phi rows are 24 floats = 96 B (16B aligned) -> 6 float4 loads per thread.
// Fixed reduction order -> deterministic.
// ---------------------------------------------------------------------------
__global__ __launch_bounds__(256) void k_reduce2(const float* __restrict__ phi) {
    __shared__ float wr[8][24];   // per-warp raw partials
    __shared__ float wssq[8];

    const int t = threadIdx.x;
    const int k = blockIdx.x * 256 + t;   // global index into [b][m] space, 0..16383
    const int m = k & 4095;               // index into phi rows
    const int w = t >> 5, lane = t & 31;

    // fold 32 chunk partials -> mean value xv for this (b, m)
    float s0 = 0.f, s1 = 0.f, s2 = 0.f, s3 = 0.f;
    #pragma unroll
    for (int c = 0; c < NCH; c += 4) {
        s0 += g_partials[(c+0) * 16384 + k];
        s1 += g_partials[(c+1) * 16384 + k];
        s2 += g_partials[(c+2) * 16384 + k];
        s3 += g_partials[(c+3) * 16384 + k];
    }
    const float xv = ((s0 + s1) + (s2 + s3)) * (1.0f / (float)SLEN);

    // per-thread contributions: xv * phi[m][j], j = 0..23  (6x float4)
    float a[24];
    const float4* prow = reinterpret_cast<const float4*>(phi + (size_t)m * 24);
    #pragma unroll
    for (int q = 0; q < 6; q++) {
        float4 pv = prow[q];
        a[q*4+0] = xv * pv.x;
        a[q*4+1] = xv * pv.y;
        a[q*4+2] = xv * pv.z;
        a[q*4+3] = xv * pv.w;
    }
    float ssq = xv * xv;

    // warp reduce all 25 values
    #pragma unroll
    for (int off = 16; off > 0; off >>= 1) {
        #pragma unroll
        for (int j = 0; j < 24; j++)
            a[j] += __shfl_down_sync(0xffffffffu, a[j], off);
        ssq += __shfl_down_sync(0xffffffffu, ssq, off);
    }
    if (lane == 0) {
        #pragma unroll
        for (int j = 0; j < 24; j++) wr[w][j] = a[j];
        wssq[w] = ssq;
    }
    __syncthreads();

    if (t < 24) {
        float v = (wr[0][t] + wr[1][t]) + (wr[2][t] + wr[3][t])
                + (wr[4][t] + wr[5][t]) + (wr[6][t] + wr[7][t]);
        g_rawp[blockIdx.x * 24 + t] = v;
    }
    if (t == 31) {
        g_ssqp[blockIdx.x] = (wssq[0] + wssq[1]) + (wssq[2] + wssq[3])
                           + (wssq[4] + wssq[5]) + (wssq[6] + wssq[7]);
    }
}

// ---------------------------------------------------------------------------
// Kernel 3: tiny finalizer. 1 block, 128 threads.
// Sum the 16 per-block partials for each batch, then threads 0..3 do the
// scalar sigmoid / normalize / 20-iter 4x4 sinkhorn.
// ---------------------------------------------------------------------------
__global__ __launch_bounds__(128) void k_small(
    const float* __restrict__ pre_base,
    const float* __restrict__ post_base,
    const float* __restrict__ res_base,
    const float* __restrict__ a_pre,
    const float* __restrict__ a_post,
    const float* __restrict__ a_res)
{
    __shared__ float rawS[96];
    __shared__ float ssqS[4];

    const int t = threadIdx.x;
    if (t < 96) {
        const int bb = t / 24, j = t - bb * 24;   // batch bb owns blocks 16*bb..16*bb+15
        float v = 0.f;
        #pragma unroll
        for (int blk = 0; blk < 16; blk++)
            v += g_rawp[(bb * 16 + blk) * 24 + j];
        rawS[t] = v;
    }
    if (t >= 96 && t < 100) {
        const int bb = t - 96;
        float v = 0.f;
        #pragma unroll
        for (int blk = 0; blk < 16; blk++)
            v += g_ssqp[bb * 16 + blk];
        ssqS[bb] = v;
    }
    __syncthreads();

    if (t < 4) {
        const int bb = t;
        float inv_rms = rsqrtf(ssqS[bb] * (1.0f / 4096.0f) + EPSV);
        float ap  = a_pre[0]  * inv_rms;
        float apo = a_post[0] * inv_rms;
        float ar  = a_res[0]  * inv_rms;
        const float* raw = &rawS[bb * 24];

        float pre[4], sum = 0.f;
        #pragma unroll
        for (int j = 0; j < 4; j++) {
            float v = fmaf(ap, raw[j], pre_base[j]);
            v = 1.0f / (1.0f + expf(-v));
            pre[j] = v; sum += v;
        }
        float inv = 1.0f / (sum + EPSV);

        float post[4];
        #pragma unroll
        for (int j = 0; j < 4; j++) {
            float v = fmaf(apo, raw[4 + j], post_base[j]);
            post[j] = 2.0f / (1.0f + expf(-v));
        }

        float P[16];
        #pragma unroll
        for (int j = 0; j < 16; j++)
            P[j] = fabsf(fmaf(ar, raw[8 + j], res_base[j])) + EPSV;
        for (int it = 0; it < 20; it++) {
            #pragma unroll
            for (int r = 0; r < 4; r++) {
                float rs = (P[4*r] + P[4*r+1]) + (P[4*r+2] + P[4*r+3]) + EPSV;
                float ir = 1.0f / rs;
                P[4*r] *= ir; P[4*r+1] *= ir; P[4*r+2] *= ir; P[4*r+3] *= ir;
            }
            #pragma unroll
            for (int cI = 0; cI < 4; cI++) {
                float cs = (P[cI] + P[4+cI]) + (P[8+cI] + P[12+cI]) + EPSV;
                float ic = 1.0f / cs;
                P[cI] *= ic; P[4+cI] *= ic; P[8+cI] *= ic; P[12+cI] *= ic;
            }
        }

        float* o = &g_coefs[bb * 24];
        #pragma unroll
        for (int j = 0; j < 4; j++)  o[j]     = pre[j] * inv;
        #pragma unroll
        for (int j = 0; j < 4; j++)  o[4 + j] = post[j];
        #pragma unroll
        for (int j = 0; j < 16; j++) o[8 + j] = P[j];
    }
}

// ---------------------------------------------------------------------------
// Kernel 4: stream mixing + residual + pack. (already at HBM roofline)
// grid = 16384 (b*s), block = 256 (one float4 of d per thread)
// ---------------------------------------------------------------------------
__global__ __launch_bounds__(256) void k_mix(const float4* __restrict__ H4,
                                             const float4* __restrict__ BO4,
                                             float4* __restrict__ out4) {
    __shared__ float c[24];
    const int bs = blockIdx.x;          // b*4096 + s
    const int b  = bs >> 12;
    const int t  = threadIdx.x;
    if (t < 24) c[t] = g_coefs[b * 24 + t];
    __syncthreads();

    const size_t hb = (size_t)bs * (NSTR * D4) + t;
    float4 h0 = H4[hb];
    float4 h1 = H4[hb + D4];
    float4 h2 = H4[hb + 2 * D4];
    float4 h3 = H4[hb + 3 * D4];
    float4 bo = BO4[(size_t)bs * D4 + t];

    const size_t ob = (size_t)bs * (5 * D4) + t;

    float4 r;
    r.x = fmaf(c[0], h0.x, fmaf(c[1], h1.x, fmaf(c[2], h2.x, c[3] * h3.x)));
    r.y = fmaf(c[0], h0.y, fmaf(c[1], h1.y, fmaf(c[2], h2.y, c[3] * h3.y)));
    r.z = fmaf(c[0], h0.z, fmaf(c[1], h1.z, fmaf(c[2], h2.z, c[3] * h3.z)));
    r.w = fmaf(c[0], h0.w, fmaf(c[1], h1.w, fmaf(c[2], h2.w, c[3] * h3.w)));
    out4[ob] = r;

    #pragma unroll
    for (int n = 0; n < 4; n++) {
        float r0 = c[8 + 4*n], r1 = c[9 + 4*n], r2 = c[10 + 4*n], r3 = c[11 + 4*n];
        float pp = c[4 + n];
        float4 o;
        o.x = fmaf(r0, h0.x, fmaf(r1, h1.x, fmaf(r2, h2.x, fmaf(r3, h3.x, pp * bo.x))));
        o.y = fmaf(r0, h0.y, fmaf(r1, h1.y, fmaf(r2, h2.y, fmaf(r3, h3.y, pp * bo.y))));
        o.z = fmaf(r0, h0.z, fmaf(r1, h1.z, fmaf(r2, h2.z, fmaf(r3, h3.z, pp * bo.z))));
        o.w = fmaf(r0, h0.w, fmaf(r1, h1.w, fmaf(r2, h2.w, fmaf(r3, h3.w, pp * bo.w))));
        out4[ob + (size_t)(1 + n) * D4] = o;
    }
}

// ---------------------------------------------------------------------------
// Inputs (metadata order): H, branch_output, phi, H_pre_base, H_post_base,
//                          H_res_base, alpha_pre, alpha_post, alpha_res
// ---------------------------------------------------------------------------
extern "C" void kernel_launch(void* const* d_in, const int* in_sizes, int n_in,
                              void* d_out, int out_size) {
    (void)in_sizes; (void)n_in; (void)out_size;
    const float4* H4  = (const float4*)d_in[0];
    const float4* BO4 = (const float4*)d_in[1];
    const float* phi  = (const float*)d_in[2];
    const float* preb = (const float*)d_in[3];
    const float* postb= (const float*)d_in[4];
    const float* resb = (const float*)d_in[5];
    const float* apre = (const float*)d_in[6];
    const float* apost= (const float*)d_in[7];
    const float* ares = (const float*)d_in[8];

    dim3 g1(NCH, NSTR, NSTR);
    k_reduce1<<<g1, 256>>>(H4);
    k_reduce2<<<64, 256>>>(phi);
    k_small<<<1, 128>>>(preb, postb, resb, apre, apost, ares);
    k_mix<<<16384, 256>>>(H4, BO4, (float4*)d_out);
}